// round 6
// baseline (speedup 1.0000x reference)
#include <cuda_runtime.h>
#include <cstdint>

// Row-wise top-k(=6) thresholded renormalization.
//   delta = (6th largest of row) + 1e-7
//   w     = max(v - delta, 0) ;  out = w / (sum(w) + 1e-7)
//
// R6: one WARP per row, persistent grid-stride loop (single wave, no
// wave-transition DRAM bubbles), w overwrites v in-place to cut registers.
//   t    = 6th largest of the 32 per-thread maxes  (provably <= true 6th)
//   cand = all elements >= t (full-row buffer => exact for ANY input)
//   v6   = 6th largest of cand (iterative extraction, exact dup handling)

#define COLS   1024
#define TOPK   6
#define EPSV   1e-7f
#define WPB    8            // warps (=rows in flight) per block
#define GRID_CAP 740        // 148 SMs * 5 blocks: one resident wave

__device__ __forceinline__ unsigned redux_max_u32(unsigned v) {
    unsigned r;
    asm volatile("redux.sync.max.u32 %0, %1, %2;"
                 : "=r"(r) : "r"(v), "r"(0xffffffffu));
    return r;
}
// monotone bijection: float ordering -> u32 ordering (exact, invertible)
__device__ __forceinline__ unsigned fkey(float f) {
    unsigned b = __float_as_uint(f);
    return b ^ ((unsigned)((int)b >> 31) | 0x80000000u);
}
__device__ __forceinline__ float funkey(unsigned k) {
    unsigned b = (k & 0x80000000u) ? (k ^ 0x80000000u) : ~k;
    return __uint_as_float(b);
}
__device__ __forceinline__ float4 fmax4(float4 a, float4 b) {
    return make_float4(fmaxf(a.x,b.x), fmaxf(a.y,b.y),
                       fmaxf(a.z,b.z), fmaxf(a.w,b.w));
}

__global__ __launch_bounds__(32 * WPB, 6)
void topk_renorm_kernel(const float* __restrict__ in,
                        float* __restrict__ out, int rows) {
    const int lane = threadIdx.x & 31;
    const int warp = threadIdx.x >> 5;

    __shared__ unsigned sh_cand[WPB][COLS];   // full-row capacity per warp
    __shared__ int      sh_cnt[WPB];

    const int row_stride = gridDim.x * WPB;

    for (int row = blockIdx.x * WPB + warp; row < rows; row += row_stride) {

        // ---- load: 32 elems/thread as 8 float4 (MLP=8) ----
        const float4* rp = reinterpret_cast<const float4*>(in + (size_t)row * COLS);
        float4 v[8];
#pragma unroll
        for (int i = 0; i < 8; ++i) v[i] = __ldcs(rp + lane + 32 * i);

        // ---- per-thread max (31 FMNMX tree) ----
        float4 m01 = fmax4(v[0], v[1]), m23 = fmax4(v[2], v[3]);
        float4 m45 = fmax4(v[4], v[5]), m67 = fmax4(v[6], v[7]);
        float4 mm  = fmax4(fmax4(m01, m23), fmax4(m45, m67));
        float lmax = fmaxf(fmaxf(mm.x, mm.y), fmaxf(mm.z, mm.w));

        // ---- t = 6th largest of the 32 thread-maxes ----
        unsigned a = fkey(lmax);
        unsigned kth = 0u;
#pragma unroll
        for (int r = 0; r < TOPK; ++r) {
            unsigned m = redux_max_u32(a);
            kth = m;
            unsigned msk = __ballot_sync(0xffffffffu, a == m);
            if (lane == (__ffs((int)msk) - 1)) a = 0u;
        }
        const float t = funkey(kth);     // identical on all lanes

        // ---- compact candidates (v >= t) into this warp's buffer ----
        if (lane == 0) sh_cnt[warp] = 0;
        __syncwarp();
        if (lmax >= t) {                 // most threads skip the whole scan
#pragma unroll
            for (int i = 0; i < 8; ++i) {
                if (v[i].x >= t) sh_cand[warp][atomicAdd(&sh_cnt[warp],1)] = fkey(v[i].x);
                if (v[i].y >= t) sh_cand[warp][atomicAdd(&sh_cnt[warp],1)] = fkey(v[i].y);
                if (v[i].z >= t) sh_cand[warp][atomicAdd(&sh_cnt[warp],1)] = fkey(v[i].z);
                if (v[i].w >= t) sh_cand[warp][atomicAdd(&sh_cnt[warp],1)] = fkey(v[i].w);
            }
        }
        __syncwarp();

        // ---- exact 6th largest of the n candidates (n >= 6) ----
        const int n = sh_cnt[warp];
        unsigned kk = 0u;
#pragma unroll 1
        for (int r = 0; r < TOPK; ++r) {
            unsigned lm = 0u;
            for (int i = lane; i < n; i += 32) lm = max(lm, sh_cand[warp][i]);
            unsigned m = redux_max_u32(lm);
            kk = m;
            int idx = -1;                      // remove exactly one instance
            for (int i = lane; i < n; i += 32)
                if (sh_cand[warp][i] == m) { idx = i; break; }
            unsigned msk = __ballot_sync(0xffffffffu, idx >= 0);
            if (lane == (__ffs((int)msk) - 1)) sh_cand[warp][idx] = 0u;
            __syncwarp();
        }
        const float delta = funkey(kk) + EPSV; // identical on all lanes

        // ---- epilogue: clamp IN PLACE, warp sum, normalize, store ----
        float4 acc = make_float4(0.f, 0.f, 0.f, 0.f);
#pragma unroll
        for (int i = 0; i < 8; ++i) {
            v[i].x = fmaxf(v[i].x - delta, 0.0f);
            v[i].y = fmaxf(v[i].y - delta, 0.0f);
            v[i].z = fmaxf(v[i].z - delta, 0.0f);
            v[i].w = fmaxf(v[i].w - delta, 0.0f);
            acc.x += v[i].x; acc.y += v[i].y; acc.z += v[i].z; acc.w += v[i].w;
        }
        float s = (acc.x + acc.y) + (acc.z + acc.w);
#pragma unroll
        for (int o = 16; o > 0; o >>= 1)
            s += __shfl_xor_sync(0xffffffffu, s, o);
        const float rinv = 1.0f / (s + EPSV);  // identical on all lanes

        float4* op = reinterpret_cast<float4*>(out + (size_t)row * COLS);
#pragma unroll
        for (int i = 0; i < 8; ++i) {
            float4 o4;
            o4.x = v[i].x * rinv; o4.y = v[i].y * rinv;
            o4.z = v[i].z * rinv; o4.w = v[i].w * rinv;
            __stcs(op + lane + 32 * i, o4);
        }
    }
}

extern "C" void kernel_launch(void* const* d_in, const int* in_sizes, int n_in,
                              void* d_out, int out_size) {
    const float* in = (const float*)d_in[0];
    float* out = (float*)d_out;
    const int rows = in_sizes[0] / COLS;           // 65536 for reference shape
    int grid = (rows + WPB - 1) / WPB;
    if (grid > GRID_CAP) grid = GRID_CAP;
    topk_renorm_kernel<<<grid, 32 * WPB>>>(in, out, rows);
}

// round 7
// speedup vs baseline: 1.1060x; 1.1060x over previous
#include <cuda_runtime.h>
#include <cstdint>

// Row-wise top-k(=6) thresholded renormalization.
//   delta = (6th largest of row) + 1e-7
//   w     = max(v - delta, 0) ;  out = w / (sum(w) + 1e-7)
//
// R7: one WARP per row, one block per 8 rows (grid=8192 — independent blocks
// pipeline better than a persistent loop, measured R6). In-place clamp cuts
// registers; launch_bounds(256,6) lifts residency to 6 blocks/SM.
//   t    = 6th largest of the 32 per-thread maxes  (provably <= true 6th)
//   cand = all elements >= t (full-row buffer => exact for ANY input)
//   v6   = 6th largest of cand (iterative extraction, exact dup handling)

#define COLS   1024
#define TOPK   6
#define EPSV   1e-7f
#define WPB    8            // warps (=rows) per block

__device__ __forceinline__ unsigned redux_max_u32(unsigned v) {
    unsigned r;
    asm volatile("redux.sync.max.u32 %0, %1, %2;"
                 : "=r"(r) : "r"(v), "r"(0xffffffffu));
    return r;
}
// monotone bijection: float ordering -> u32 ordering (exact, invertible)
__device__ __forceinline__ unsigned fkey(float f) {
    unsigned b = __float_as_uint(f);
    return b ^ ((unsigned)((int)b >> 31) | 0x80000000u);
}
__device__ __forceinline__ float funkey(unsigned k) {
    unsigned b = (k & 0x80000000u) ? (k ^ 0x80000000u) : ~k;
    return __uint_as_float(b);
}
__device__ __forceinline__ float4 fmax4(float4 a, float4 b) {
    return make_float4(fmaxf(a.x,b.x), fmaxf(a.y,b.y),
                       fmaxf(a.z,b.z), fmaxf(a.w,b.w));
}

__global__ __launch_bounds__(32 * WPB, 6)
void topk_renorm_kernel(const float* __restrict__ in,
                        float* __restrict__ out, int rows) {
    const int lane = threadIdx.x & 31;
    const int warp = threadIdx.x >> 5;
    const int row  = blockIdx.x * WPB + warp;
    if (row >= rows) return;

    __shared__ unsigned sh_cand[WPB][COLS];   // full-row capacity per warp
    __shared__ int      sh_cnt[WPB];

    // ---- load: 32 elems/thread as 8 float4 (MLP=8) ----
    const float4* rp = reinterpret_cast<const float4*>(in + (size_t)row * COLS);
    float4 v[8];
#pragma unroll
    for (int i = 0; i < 8; ++i) v[i] = __ldcs(rp + lane + 32 * i);

    // ---- per-thread max (31 FMNMX tree) ----
    float4 m01 = fmax4(v[0], v[1]), m23 = fmax4(v[2], v[3]);
    float4 m45 = fmax4(v[4], v[5]), m67 = fmax4(v[6], v[7]);
    float4 mm  = fmax4(fmax4(m01, m23), fmax4(m45, m67));
    float lmax = fmaxf(fmaxf(mm.x, mm.y), fmaxf(mm.z, mm.w));

    // ---- t = 6th largest of the 32 thread-maxes ----
    unsigned a = fkey(lmax);
    unsigned kth = 0u;
#pragma unroll
    for (int r = 0; r < TOPK; ++r) {
        unsigned m = redux_max_u32(a);
        kth = m;
        unsigned msk = __ballot_sync(0xffffffffu, a == m);
        if (lane == (__ffs((int)msk) - 1)) a = 0u;
    }
    const float t = funkey(kth);     // identical on all lanes

    // ---- compact candidates (v >= t) into this warp's buffer ----
    if (lane == 0) sh_cnt[warp] = 0;
    __syncwarp();
    if (lmax >= t) {                 // most threads skip the whole scan
#pragma unroll
        for (int i = 0; i < 8; ++i) {
            if (v[i].x >= t) sh_cand[warp][atomicAdd(&sh_cnt[warp],1)] = fkey(v[i].x);
            if (v[i].y >= t) sh_cand[warp][atomicAdd(&sh_cnt[warp],1)] = fkey(v[i].y);
            if (v[i].z >= t) sh_cand[warp][atomicAdd(&sh_cnt[warp],1)] = fkey(v[i].z);
            if (v[i].w >= t) sh_cand[warp][atomicAdd(&sh_cnt[warp],1)] = fkey(v[i].w);
        }
    }
    __syncwarp();

    // ---- exact 6th largest of the n candidates (n >= 6) ----
    const int n = sh_cnt[warp];
    unsigned kk = 0u;
#pragma unroll 1
    for (int r = 0; r < TOPK; ++r) {
        unsigned lm = 0u;
        for (int i = lane; i < n; i += 32) lm = max(lm, sh_cand[warp][i]);
        unsigned m = redux_max_u32(lm);
        kk = m;
        int idx = -1;                          // remove exactly one instance
        for (int i = lane; i < n; i += 32)
            if (sh_cand[warp][i] == m) { idx = i; break; }
        unsigned msk = __ballot_sync(0xffffffffu, idx >= 0);
        if (lane == (__ffs((int)msk) - 1)) sh_cand[warp][idx] = 0u;
        __syncwarp();
    }
    const float delta = funkey(kk) + EPSV;     // identical on all lanes

    // ---- epilogue: clamp IN PLACE, warp sum, normalize, store ----
    float4 acc = make_float4(0.f, 0.f, 0.f, 0.f);
#pragma unroll
    for (int i = 0; i < 8; ++i) {
        v[i].x = fmaxf(v[i].x - delta, 0.0f);
        v[i].y = fmaxf(v[i].y - delta, 0.0f);
        v[i].z = fmaxf(v[i].z - delta, 0.0f);
        v[i].w = fmaxf(v[i].w - delta, 0.0f);
        acc.x += v[i].x; acc.y += v[i].y; acc.z += v[i].z; acc.w += v[i].w;
    }
    float s = (acc.x + acc.y) + (acc.z + acc.w);
#pragma unroll
    for (int o = 16; o > 0; o >>= 1)
        s += __shfl_xor_sync(0xffffffffu, s, o);
    const float rinv = 1.0f / (s + EPSV);      // identical on all lanes

    float4* op = reinterpret_cast<float4*>(out + (size_t)row * COLS);
#pragma unroll
    for (int i = 0; i < 8; ++i) {
        float4 o4;
        o4.x = v[i].x * rinv; o4.y = v[i].y * rinv;
        o4.z = v[i].z * rinv; o4.w = v[i].w * rinv;
        __stcs(op + lane + 32 * i, o4);
    }
}

extern "C" void kernel_launch(void* const* d_in, const int* in_sizes, int n_in,
                              void* d_out, int out_size) {
    const float* in = (const float*)d_in[0];
    float* out = (float*)d_out;
    const int rows = in_sizes[0] / COLS;           // 65536 for reference shape
    const int grid = (rows + WPB - 1) / WPB;
    topk_renorm_kernel<<<grid, 32 * WPB>>>(in, out, rows);
}

// round 8
// speedup vs baseline: 1.5107x; 1.3659x over previous
#include <cuda_runtime.h>
#include <cstdint>

// Row-wise top-k(=6) thresholded renormalization.
//   delta = (6th largest of row) + 1e-7
//   w     = max(v - delta, 0) ;  out = w / (sum(w) + 1e-7)
//
// R8: R5 structure exactly (one warp per row, grid=rows/8, NO register
// constraint — 47 regs keeps all 8 LDG.128 in flight, measured critical).
// Change vs R5: candidate-selection stage D is a single-lane insertion
// top-6 (n is tiny) instead of 6 warp-collective extraction rounds.
//   t    = 6th largest of the 32 per-thread maxes  (provably <= true 6th)
//   cand = all elements >= t (full-row buffer => exact for ANY input)
//   v6   = 6th largest of cand (insertion sort, exact dup handling)

#define COLS   1024
#define TOPK   6
#define EPSV   1e-7f
#define WPB    8            // warps (=rows) per block

__device__ __forceinline__ unsigned redux_max_u32(unsigned v) {
    unsigned r;
    asm volatile("redux.sync.max.u32 %0, %1, %2;"
                 : "=r"(r) : "r"(v), "r"(0xffffffffu));
    return r;
}
// monotone bijection: float ordering -> u32 ordering (exact, invertible)
__device__ __forceinline__ unsigned fkey(float f) {
    unsigned b = __float_as_uint(f);
    return b ^ ((unsigned)((int)b >> 31) | 0x80000000u);
}
__device__ __forceinline__ float funkey(unsigned k) {
    unsigned b = (k & 0x80000000u) ? (k ^ 0x80000000u) : ~k;
    return __uint_as_float(b);
}
__device__ __forceinline__ float4 fmax4(float4 a, float4 b) {
    return make_float4(fmaxf(a.x,b.x), fmaxf(a.y,b.y),
                       fmaxf(a.z,b.z), fmaxf(a.w,b.w));
}

__global__ __launch_bounds__(32 * WPB)
void topk_renorm_kernel(const float* __restrict__ in,
                        float* __restrict__ out, int rows) {
    const int lane = threadIdx.x & 31;
    const int warp = threadIdx.x >> 5;
    const int row  = blockIdx.x * WPB + warp;
    if (row >= rows) return;

    __shared__ unsigned sh_cand[WPB][COLS];   // full-row capacity per warp
    __shared__ int      sh_cnt[WPB];

    // ---- load: 32 elems/thread as 8 float4 (MLP=8) ----
    const float4* rp = reinterpret_cast<const float4*>(in + (size_t)row * COLS);
    float4 v[8];
#pragma unroll
    for (int i = 0; i < 8; ++i) v[i] = __ldcs(rp + lane + 32 * i);

    // ---- per-thread max (31 FMNMX tree) ----
    float4 m01 = fmax4(v[0], v[1]), m23 = fmax4(v[2], v[3]);
    float4 m45 = fmax4(v[4], v[5]), m67 = fmax4(v[6], v[7]);
    float4 mm  = fmax4(fmax4(m01, m23), fmax4(m45, m67));
    float lmax = fmaxf(fmaxf(mm.x, mm.y), fmaxf(mm.z, mm.w));

    // ---- t = 6th largest of the 32 thread-maxes ----
    unsigned a = fkey(lmax);
    unsigned kth = 0u;
#pragma unroll
    for (int r = 0; r < TOPK; ++r) {
        unsigned m = redux_max_u32(a);
        kth = m;
        unsigned msk = __ballot_sync(0xffffffffu, a == m);
        if (lane == (__ffs((int)msk) - 1)) a = 0u;
    }
    const float t = funkey(kth);     // identical on all lanes

    // ---- compact candidates (v >= t) into this warp's buffer ----
    if (lane == 0) sh_cnt[warp] = 0;
    __syncwarp();
    if (lmax >= t) {                 // most threads skip the whole scan
#pragma unroll
        for (int i = 0; i < 8; ++i) {
            if (v[i].x >= t) sh_cand[warp][atomicAdd(&sh_cnt[warp],1)] = fkey(v[i].x);
            if (v[i].y >= t) sh_cand[warp][atomicAdd(&sh_cnt[warp],1)] = fkey(v[i].y);
            if (v[i].z >= t) sh_cand[warp][atomicAdd(&sh_cnt[warp],1)] = fkey(v[i].z);
            if (v[i].w >= t) sh_cand[warp][atomicAdd(&sh_cnt[warp],1)] = fkey(v[i].w);
        }
    }
    __syncwarp();

    // ---- 6th largest of the n candidates: lane-0 insertion top-6 ----
    // (n >= 6 by construction; n is typically ~7, worst case COLS)
    float delta;
    if (lane == 0) {
        const int n = sh_cnt[warp];
        unsigned s0=0u,s1=0u,s2=0u,s3=0u,s4=0u,s5=0u;   // s0 >= ... >= s5
        for (int i = 0; i < n; ++i) {
            unsigned x = sh_cand[warp][i];
            if (x > s5) {
                if      (x > s0) { s5=s4;s4=s3;s3=s2;s2=s1;s1=s0;s0=x; }
                else if (x > s1) { s5=s4;s4=s3;s3=s2;s2=s1;s1=x; }
                else if (x > s2) { s5=s4;s4=s3;s3=s2;s2=x; }
                else if (x > s3) { s5=s4;s4=s3;s3=x; }
                else if (x > s4) { s5=s4;s4=x; }
                else             { s5=x; }
            }
        }
        delta = funkey(s5) + EPSV;
    }
    delta = __shfl_sync(0xffffffffu, delta, 0);   // broadcast to the warp

    // ---- epilogue: clamp, warp sum, normalize, store ----
    float4 w[8];
    float4 acc = make_float4(0.f, 0.f, 0.f, 0.f);
#pragma unroll
    for (int i = 0; i < 8; ++i) {
        w[i].x = fmaxf(v[i].x - delta, 0.0f);
        w[i].y = fmaxf(v[i].y - delta, 0.0f);
        w[i].z = fmaxf(v[i].z - delta, 0.0f);
        w[i].w = fmaxf(v[i].w - delta, 0.0f);
        acc.x += w[i].x; acc.y += w[i].y; acc.z += w[i].z; acc.w += w[i].w;
    }
    float s = (acc.x + acc.y) + (acc.z + acc.w);
#pragma unroll
    for (int o = 16; o > 0; o >>= 1)
        s += __shfl_xor_sync(0xffffffffu, s, o);
    const float rinv = 1.0f / (s + EPSV);      // identical on all lanes

    float4* op = reinterpret_cast<float4*>(out + (size_t)row * COLS);
#pragma unroll
    for (int i = 0; i < 8; ++i) {
        float4 o4;
        o4.x = w[i].x * rinv; o4.y = w[i].y * rinv;
        o4.z = w[i].z * rinv; o4.w = w[i].w * rinv;
        __stcs(op + lane + 32 * i, o4);
    }
}

extern "C" void kernel_launch(void* const* d_in, const int* in_sizes, int n_in,
                              void* d_out, int out_size) {
    const float* in = (const float*)d_in[0];
    float* out = (float*)d_out;
    const int rows = in_sizes[0] / COLS;           // 65536 for reference shape
    const int grid = (rows + WPB - 1) / WPB;
    topk_renorm_kernel<<<grid, 32 * WPB>>>(in, out, rows);
}